// round 2
// baseline (speedup 1.0000x reference)
#include <cuda_runtime.h>
#include <cuda_fp16.h>
#include <cstdint>

// ---------------------------------------------------------------------------
// MILAttention on sm_100 (baseline PTX: mma.sync fp16, ldmatrix, cp.async).
//
// logits[b,p] = sum_i tanh(x.V_w[i]+Vb[i]) * sigmoid(x.U_w[i]+Ub[i]) * ww[i] + wb
// out[b,1,p]  = masked softmax over first nonpad[b] positions.
//
// GEMM: M=65536 (128/CTA), N=512 interleaved (2i=V ch i, 2i+1=U ch i),
// K=768 in chunks of 64, fp16 operands / f32 accum (error ~1.3e-4, OK).
// N split in 2 chunks of 256 (register pressure); gating epilogue folds each
// chunk into per-row logits in smem.
// ---------------------------------------------------------------------------

#define BZ 8
#define PZ 8192
#define FZ 768
#define FI 256

static constexpr int M_TILE  = 128;
static constexpr int THREADS = 256;       // 8 warps: 2(M) x 4(N), warp tile 64x64
static constexpr int GRID    = (BZ * PZ) / M_TILE;   // 512
static constexpr int KC      = 64;
static constexpr int NCH     = 256;       // N per chunk
static constexpr int KCHUNKS = FZ / KC;   // 12
static constexpr int TOTCH   = 2 * KCHUNKS;  // 24 (nchunk-major)

// fp16 smem tiles: row stride 72 halves = 144 B (conflict-free ldmatrix)
static constexpr int SA_STRIDE_B = 144;

// smem byte offsets
static constexpr int OFF_ASTG0 = 0;                    // 128x64 f32 = 32768
static constexpr int OFF_ASTG1 = 32768;
static constexpr int OFF_AS0   = 65536;                // 128x72 fp16 = 18432
static constexpr int OFF_AS1   = 83968;
static constexpr int OFF_BS0   = 102400;               // 256x72 fp16 = 36864
static constexpr int OFF_BS1   = 139264;
static constexpr int OFF_LOG   = 176128;               // 128 f32
static constexpr int OFF_VB    = 176640;               // 256 f32
static constexpr int OFF_UB    = 177664;
static constexpr int OFF_WW    = 178688;
static constexpr int SMEM_TOTAL = 179712;

__device__ __half g_wI[2 * FI * FZ];   // interleaved fp16 weights [512][768]
__device__ float  g_att[BZ * PZ];      // logits

// ---------------- small helpers ----------------
__device__ __forceinline__ uint32_t smem_u32(const void* p) {
    uint32_t a;
    asm("{ .reg .u64 t; cvta.to.shared.u64 t, %1; cvt.u32.u64 %0, t; }" : "=r"(a) : "l"(p));
    return a;
}
__device__ __forceinline__ void cp16(uint32_t dst, const void* src) {
    asm volatile("cp.async.cg.shared.global [%0], [%1], 16;" :: "r"(dst), "l"(src));
}
__device__ __forceinline__ void cp_commit() {
    asm volatile("cp.async.commit_group;" ::: "memory");
}
__device__ __forceinline__ void cp_wait0() {
    asm volatile("cp.async.wait_group 0;" ::: "memory");
}
__device__ __forceinline__ void ldsm4(uint32_t& r0, uint32_t& r1, uint32_t& r2, uint32_t& r3,
                                      uint32_t addr) {
    asm volatile("ldmatrix.sync.aligned.m8n8.x4.shared.b16 {%0,%1,%2,%3}, [%4];"
                 : "=r"(r0), "=r"(r1), "=r"(r2), "=r"(r3) : "r"(addr));
}
__device__ __forceinline__ void mma16816(float* c, const uint32_t* a, const uint32_t* b) {
    asm volatile("mma.sync.aligned.m16n8k16.row.col.f32.f16.f16.f32 "
                 "{%0,%1,%2,%3}, {%4,%5,%6,%7}, {%8,%9}, {%0,%1,%2,%3};"
                 : "+f"(c[0]), "+f"(c[1]), "+f"(c[2]), "+f"(c[3])
                 : "r"(a[0]), "r"(a[1]), "r"(a[2]), "r"(a[3]), "r"(b[0]), "r"(b[1]));
}
__device__ __forceinline__ float tanha(float x) {
    float y;
    asm("tanh.approx.f32 %0, %1;" : "=f"(y) : "f"(x));
    return y;
}

// ---------------- weight prep: f32 -> interleaved fp16 ----------------
__global__ void __launch_bounds__(256) prep_w_kernel(const float* __restrict__ V_w,
                                                     const float* __restrict__ U_w) {
    int i = blockIdx.x * 256 + threadIdx.x;       // 512*768 total
    int r = i / FZ, k = i - r * FZ;
    const float* src = (r & 1) ? U_w : V_w;
    g_wI[i] = __float2half_rn(src[(r >> 1) * FZ + k]);
}

// ---------------- GEMM + gating ----------------
__global__ void __launch_bounds__(THREADS) mil_gemm_kernel(
    const float* __restrict__ x,
    const float* __restrict__ V_b, const float* __restrict__ U_b,
    const float* __restrict__ w_w, const float* __restrict__ w_b) {
    extern __shared__ char smem[];
    const uint32_t sb = smem_u32(smem);
    const int tid  = threadIdx.x;
    const int wid  = tid >> 5;
    const int lane = tid & 31;
    const int wm = wid >> 2;          // 0..1  -> rows wm*64
    const int wn = wid & 3;           // 0..3  -> cols wn*64 (within 256 chunk)
    const int m0 = wm * 64;
    const int n0 = wn * 64;

    float* slog = reinterpret_cast<float*>(smem + OFF_LOG);
    float* sVb  = reinterpret_cast<float*>(smem + OFF_VB);
    float* sUb  = reinterpret_cast<float*>(smem + OFF_UB);
    float* sww  = reinterpret_cast<float*>(smem + OFF_WW);
    if (tid < 128) slog[tid] = 0.0f;
    sVb[tid] = V_b[tid];
    sUb[tid] = U_b[tid];
    sww[tid] = w_w[tid];

    const int baseRow = blockIdx.x * M_TILE;
    // per-thread load indices (8 iters each)
    const int arow = tid >> 4, aq = tid & 15;       // A: row, float4-slot (strided by 16 rows)
    const int brow = tid >> 3, bkc = tid & 7;       // B: row, 16B-slot (strided by 32 rows)

    // ---- issue loads for chunk cc into stage s ----
    auto issue_loads = [&](int cc, int s) {
        const int kb = (cc % KCHUNKS) * KC;
        const int nb = (cc / KCHUNKS) * NCH;
        const uint32_t astg = sb + (s ? OFF_ASTG1 : OFF_ASTG0);
        const uint32_t bsm  = sb + (s ? OFF_BS1 : OFF_BS0);
        const float* asrc0 = x + (size_t)(baseRow + arow) * FZ + kb + aq * 4;
        #pragma unroll
        for (int t = 0; t < 8; ++t) {
            cp16(astg + (uint32_t)((arow + t * 16) * 256 + aq * 16),
                 asrc0 + (size_t)t * 16 * FZ);
        }
        const __half* bsrc0 = g_wI + (size_t)(nb + brow) * FZ + kb + bkc * 8;
        #pragma unroll
        for (int t = 0; t < 8; ++t) {
            cp16(bsm + (uint32_t)((brow + t * 32) * SA_STRIDE_B + bkc * 16),
                 bsrc0 + (size_t)t * 32 * FZ);
        }
        cp_commit();
    };
    // ---- convert staged f32 A -> padded fp16 A ----
    auto convert_A = [&](int s) {
        const float4* src = reinterpret_cast<const float4*>(smem + (s ? OFF_ASTG1 : OFF_ASTG0));
        char* dst = smem + (s ? OFF_AS1 : OFF_AS0);
        #pragma unroll
        for (int t = 0; t < 8; ++t) {
            const int r = arow + t * 16;
            float4 f = src[r * 16 + aq];
            __half2 h0 = __floats2half2_rn(f.x, f.y);
            __half2 h1 = __floats2half2_rn(f.z, f.w);
            uint2 hv;
            hv.x = *reinterpret_cast<uint32_t*>(&h0);
            hv.y = *reinterpret_cast<uint32_t*>(&h1);
            *reinterpret_cast<uint2*>(dst + r * SA_STRIDE_B + aq * 8) = hv;
        }
    };

    // prologue: chunk 0 -> stage 0
    issue_loads(0, 0);
    cp_wait0();
    __syncthreads();
    convert_A(0);
    __syncthreads();

    float c[4][8][4];
    #pragma unroll
    for (int mt = 0; mt < 4; ++mt)
        #pragma unroll
        for (int nt = 0; nt < 8; ++nt)
            #pragma unroll
            for (int j = 0; j < 4; ++j) c[mt][nt][j] = 0.0f;

    // lane-invariant fragment address bases
    const uint32_t aoff = (uint32_t)((m0 + (lane & 15)) * SA_STRIDE_B + (lane >> 4) * 16);
    const uint32_t boff = (uint32_t)((n0 + (lane & 15)) * SA_STRIDE_B + (lane >> 4) * 16);

    #pragma unroll 1
    for (int cc = 0; cc < TOTCH; ++cc) {
        const int bufsel = cc & 1;
        if (cc < TOTCH - 1) issue_loads(cc + 1, bufsel ^ 1);

        const uint32_t abase = sb + (bufsel ? OFF_AS1 : OFF_AS0) + aoff;
        const uint32_t bbase = sb + (bufsel ? OFF_BS1 : OFF_BS0) + boff;
        #pragma unroll
        for (int ks = 0; ks < KC / 16; ++ks) {
            uint32_t a[4][4], b[8][2];
            #pragma unroll
            for (int mt = 0; mt < 4; ++mt)
                ldsm4(a[mt][0], a[mt][1], a[mt][2], a[mt][3],
                      abase + (uint32_t)(mt * 16 * SA_STRIDE_B + ks * 32));
            #pragma unroll
            for (int nt2 = 0; nt2 < 4; ++nt2) {
                uint32_t r0, r1, r2, r3;
                ldsm4(r0, r1, r2, r3,
                      bbase + (uint32_t)(nt2 * 16 * SA_STRIDE_B + ks * 32));
                b[nt2 * 2][0] = r0;  b[nt2 * 2][1] = r2;
                b[nt2 * 2 + 1][0] = r1;  b[nt2 * 2 + 1][1] = r3;
            }
            #pragma unroll
            for (int mt = 0; mt < 4; ++mt)
                #pragma unroll
                for (int nt = 0; nt < 8; ++nt)
                    mma16816(c[mt][nt], a[mt], b[nt]);
        }

        // gating epilogue at the end of each N-chunk
        if (cc == KCHUNKS - 1 || cc == TOTCH - 1) {
            const int nc = cc / KCHUNKS;
            const int g = lane >> 2, tig = lane & 3;
            float racc[8];
            #pragma unroll
            for (int i = 0; i < 8; ++i) racc[i] = 0.0f;
            #pragma unroll
            for (int mt = 0; mt < 4; ++mt) {
                #pragma unroll
                for (int nt = 0; nt < 8; ++nt) {
                    const int ch = nc * 128 + ((n0 + nt * 8) >> 1) + tig;
                    const float vb = sVb[ch], ub = sUb[ch], wwc = sww[ch];
                    float tv0 = tanha(c[mt][nt][0] + vb);
                    float su0 = 0.5f * tanha(0.5f * (c[mt][nt][1] + ub)) + 0.5f;
                    float tv1 = tanha(c[mt][nt][2] + vb);
                    float su1 = 0.5f * tanha(0.5f * (c[mt][nt][3] + ub)) + 0.5f;
                    racc[mt * 2]     += tv0 * su0 * wwc;
                    racc[mt * 2 + 1] += tv1 * su1 * wwc;
                    c[mt][nt][0] = 0.0f; c[mt][nt][1] = 0.0f;
                    c[mt][nt][2] = 0.0f; c[mt][nt][3] = 0.0f;
                }
            }
            #pragma unroll
            for (int i = 0; i < 8; ++i) {
                float v = racc[i];
                v += __shfl_xor_sync(0xffffffffu, v, 1);
                v += __shfl_xor_sync(0xffffffffu, v, 2);
                if (tig == 0) {
                    const int r = m0 + (i >> 1) * 16 + g + (i & 1) * 8;
                    atomicAdd(&slog[r], v);
                }
            }
        }

        if (cc < TOTCH - 1) {
            cp_wait0();
            __syncthreads();
            convert_A(bufsel ^ 1);
            __syncthreads();
        }
    }

    __syncthreads();
    if (tid < 128) g_att[baseRow + tid] = slog[tid] + w_b[0];
}

// ---------------- masked softmax ----------------
__global__ void __launch_bounds__(1024) mil_softmax_kernel(const int* __restrict__ npw,
                                                           float* __restrict__ out) {
    __shared__ float red[1024];
    const int b = blockIdx.x;
    const int t = threadIdx.x;
    // nonpad may be int64 (values in [1,8192] => odd words zero) or int32.
    const bool is64 = (npw[1] == 0) && (npw[3] == 0) && (npw[5] == 0) && (npw[7] == 0);
    const int np = is64 ? npw[2 * b] : npw[b];
    const float* a = g_att + b * PZ;
    float* o = out + b * PZ;

    float e[8];
    float mx = -3.4e38f;
    #pragma unroll
    for (int j = 0; j < 8; ++j) {
        int p = t + j * 1024;
        float v = (p < np) ? a[p] : -3.4e38f;
        e[j] = v;
        mx = fmaxf(mx, v);
    }
    red[t] = mx;
    __syncthreads();
    for (int s = 512; s > 0; s >>= 1) {
        if (t < s) red[t] = fmaxf(red[t], red[t + s]);
        __syncthreads();
    }
    mx = red[0];
    __syncthreads();

    float sum = 0.0f;
    #pragma unroll
    for (int j = 0; j < 8; ++j) {
        int p = t + j * 1024;
        float v = (p < np) ? expf(e[j] - mx) : 0.0f;
        e[j] = v;
        sum += v;
    }
    red[t] = sum;
    __syncthreads();
    for (int s = 512; s > 0; s >>= 1) {
        if (t < s) red[t] += red[t + s];
        __syncthreads();
    }
    const float inv = 1.0f / red[0];
    #pragma unroll
    for (int j = 0; j < 8; ++j) {
        o[t + j * 1024] = e[j] * inv;
    }
}

// ---------------- launch ----------------
extern "C" void kernel_launch(void* const* d_in, const int* in_sizes, int n_in,
                              void* d_out, int out_size) {
    (void)in_sizes; (void)n_in; (void)out_size;
    const float* x   = (const float*)d_in[0];
    const int*   npw = (const int*)d_in[1];
    const float* V_w = (const float*)d_in[2];
    const float* V_b = (const float*)d_in[3];
    const float* U_w = (const float*)d_in[4];
    const float* U_b = (const float*)d_in[5];
    const float* w_w = (const float*)d_in[6];
    const float* w_b = (const float*)d_in[7];
    float* out = (float*)d_out;

    cudaFuncSetAttribute(mil_gemm_kernel,
                         cudaFuncAttributeMaxDynamicSharedMemorySize, SMEM_TOTAL);

    prep_w_kernel<<<(2 * FI * FZ) / 256, 256>>>(V_w, U_w);
    mil_gemm_kernel<<<GRID, THREADS, SMEM_TOTAL>>>(x, V_b, U_b, w_w, w_b);
    mil_softmax_kernel<<<BZ, 1024>>>(npw, out);
}

// round 4
// speedup vs baseline: 1.2551x; 1.2551x over previous
#include <cuda_runtime.h>
#include <cuda_fp16.h>
#include <cstdint>

// ---------------------------------------------------------------------------
// MILAttention on sm_100 (mma.sync fp16 path).
//
// logits[b,p] = sum_i tanh(x.V[i]+Vb) * sigmoid(x.U[i]+Ub) * ww[i]   (+wb: no
// effect under softmax, dropped). out[b,1,p] = masked softmax over nonpad[b].
//
// GEMM: M=65536 (128 rows/CTA-pair-tile), N=512 interleaved (2i=V ch i,
// 2i+1=U ch i) split across CTA pairs (256 each), K=768 in 12 chunks of 64.
// A: LDG f32 -> regs -> fp16 smem (no staging). B: pre-converted fp16,
// cp.async. fp16 operands / f32 accum. Gating epilogue folds each CTA's
// channel-half into partial logits; softmax sums the two planes.
// ---------------------------------------------------------------------------

#define BZ 8
#define PZ 8192
#define FZ 768
#define FI 256

static constexpr int M_TILE  = 128;
static constexpr int THREADS = 256;        // 8 warps: 2(M) x 4(N), warp tile 64x64
static constexpr int GRID    = 2 * (BZ * PZ) / M_TILE;   // 1024
static constexpr int KC      = 64;
static constexpr int KCHUNKS = FZ / KC;    // 12

static constexpr int STRIDE_B = 144;       // fp16 row stride bytes (72 halves)

// smem byte offsets
static constexpr int OFF_AS0 = 0;                 // 128*144 = 18432
static constexpr int OFF_AS1 = 18432;
static constexpr int OFF_BS0 = 36864;             // 256*144 = 36864
static constexpr int OFF_BS1 = 73728;
static constexpr int OFF_LOG = 110592;            // 128 f32
static constexpr int OFF_VB  = 111104;            // 128 f32 (this CTA's half)
static constexpr int OFF_UB  = 111616;
static constexpr int OFF_WW  = 112128;
static constexpr int SMEM_TOTAL = 112640;

__device__ __half g_wI[2 * FI * FZ];     // interleaved fp16 weights [512][768]
__device__ float  g_att2[2][BZ * PZ];    // partial logits per N-half

// ---------------- helpers ----------------
__device__ __forceinline__ uint32_t smem_u32(const void* p) {
    uint32_t a;
    asm("{ .reg .u64 t; cvta.to.shared.u64 t, %1; cvt.u32.u64 %0, t; }" : "=r"(a) : "l"(p));
    return a;
}
__device__ __forceinline__ void cp16(uint32_t dst, const void* src) {
    asm volatile("cp.async.cg.shared.global [%0], [%1], 16;" :: "r"(dst), "l"(src));
}
__device__ __forceinline__ void cp_commit() {
    asm volatile("cp.async.commit_group;" ::: "memory");
}
__device__ __forceinline__ void cp_wait0() {
    asm volatile("cp.async.wait_group 0;" ::: "memory");
}
__device__ __forceinline__ void ldsm4(uint32_t& r0, uint32_t& r1, uint32_t& r2, uint32_t& r3,
                                      uint32_t addr) {
    asm volatile("ldmatrix.sync.aligned.m8n8.x4.shared.b16 {%0,%1,%2,%3}, [%4];"
                 : "=r"(r0), "=r"(r1), "=r"(r2), "=r"(r3) : "r"(addr));
}
__device__ __forceinline__ void mma16816(float* c, const uint32_t* a, const uint32_t* b) {
    asm volatile("mma.sync.aligned.m16n8k16.row.col.f32.f16.f16.f32 "
                 "{%0,%1,%2,%3}, {%4,%5,%6,%7}, {%8,%9}, {%0,%1,%2,%3};"
                 : "+f"(c[0]), "+f"(c[1]), "+f"(c[2]), "+f"(c[3])
                 : "r"(a[0]), "r"(a[1]), "r"(a[2]), "r"(a[3]), "r"(b[0]), "r"(b[1]));
}
__device__ __forceinline__ float tanha(float x) {
    float y;
    asm("tanh.approx.f32 %0, %1;" : "=f"(y) : "f"(x));
    return y;
}

// ---------------- weight prep: f32 -> interleaved fp16 ----------------
__global__ void __launch_bounds__(256) prep_w_kernel(const float* __restrict__ V_w,
                                                     const float* __restrict__ U_w) {
    int i = blockIdx.x * 256 + threadIdx.x;       // 512*768 total
    int r = i / FZ, k = i - r * FZ;
    const float* src = (r & 1) ? U_w : V_w;
    g_wI[i] = __float2half_rn(src[(r >> 1) * FZ + k]);
}

// ---------------- GEMM + gating ----------------
__global__ void __launch_bounds__(THREADS) mil_gemm_kernel(
    const float* __restrict__ x,
    const float* __restrict__ V_b, const float* __restrict__ U_b,
    const float* __restrict__ w_w) {
    extern __shared__ char smem[];
    const uint32_t sb = smem_u32(smem);
    const int tid  = threadIdx.x;
    const int wid  = tid >> 5;
    const int lane = tid & 31;
    const int wm = wid >> 2;          // 0..1 -> rows wm*64
    const int wn = wid & 3;           // 0..3 -> cols wn*64
    const int m0 = wm * 64;
    const int n0 = wn * 64;

    const int tile = blockIdx.x >> 1;
    const int nc   = blockIdx.x & 1;         // channel half: ch nc*128..nc*128+127
    const int baseRow = tile * M_TILE;
    const int nb = nc * 256;                 // B row base in g_wI

    float* slog = reinterpret_cast<float*>(smem + OFF_LOG);
    float* sVb  = reinterpret_cast<float*>(smem + OFF_VB);
    float* sUb  = reinterpret_cast<float*>(smem + OFF_UB);
    float* sww  = reinterpret_cast<float*>(smem + OFF_WW);
    if (tid < 128) {
        slog[tid] = 0.0f;
        sVb[tid] = V_b[nc * 128 + tid];
        sUb[tid] = U_b[nc * 128 + tid];
        sww[tid] = w_w[nc * 128 + tid];
    }

    // load-index mapping
    const int arow = tid >> 4, aq = tid & 15;     // A: 16 rows x 16 float4-slots, x8 row-steps
    const int brow = tid >> 3, bkc = tid & 7;     // B: 32 rows x 8 16B-slots, x8 row-steps

    // ---- B cp.async for chunk cc into stage s ----
    auto issue_B = [&](int cc, int s) {
        const int kb = cc * KC;
        const uint32_t bsm = sb + (s ? OFF_BS1 : OFF_BS0);
        const __half* bsrc0 = g_wI + (size_t)(nb + brow) * FZ + kb + bkc * 8;
        #pragma unroll
        for (int t = 0; t < 8; ++t) {
            cp16(bsm + (uint32_t)((brow + t * 32) * STRIDE_B + bkc * 16),
                 bsrc0 + (size_t)t * 32 * FZ);
        }
        cp_commit();
    };
    // ---- A LDG for chunk cc into regs ----
    float4 areg[8];
    auto load_A = [&](int cc) {
        const int kb = cc * KC;
        const float* asrc0 = x + (size_t)(baseRow + arow) * FZ + kb + aq * 4;
        #pragma unroll
        for (int t = 0; t < 8; ++t) {
            areg[t] = *reinterpret_cast<const float4*>(asrc0 + (size_t)t * 16 * FZ);
        }
    };
    // ---- convert regs -> fp16 A tile stage s ----
    auto store_A = [&](int s) {
        char* dst = smem + (s ? OFF_AS1 : OFF_AS0);
        #pragma unroll
        for (int t = 0; t < 8; ++t) {
            const int r = arow + t * 16;
            __half2 h0 = __floats2half2_rn(areg[t].x, areg[t].y);
            __half2 h1 = __floats2half2_rn(areg[t].z, areg[t].w);
            uint2 hv;
            hv.x = *reinterpret_cast<uint32_t*>(&h0);
            hv.y = *reinterpret_cast<uint32_t*>(&h1);
            *reinterpret_cast<uint2*>(dst + r * STRIDE_B + aq * 8) = hv;
        }
    };

    // prologue: chunk 0
    issue_B(0, 0);
    load_A(0);
    store_A(0);
    cp_wait0();
    __syncthreads();

    float c[4][8][4];
    #pragma unroll
    for (int mt = 0; mt < 4; ++mt)
        #pragma unroll
        for (int nt = 0; nt < 8; ++nt)
            #pragma unroll
            for (int j = 0; j < 4; ++j) c[mt][nt][j] = 0.0f;

    const uint32_t aoff = (uint32_t)((m0 + (lane & 15)) * STRIDE_B + (lane >> 4) * 16);
    const uint32_t boff = (uint32_t)((n0 + (lane & 15)) * STRIDE_B + (lane >> 4) * 16);

    #pragma unroll 1
    for (int cc = 0; cc < KCHUNKS; ++cc) {
        const int s = cc & 1;
        if (cc < KCHUNKS - 1) {
            issue_B(cc + 1, s ^ 1);
            load_A(cc + 1);
        }

        const uint32_t abase = sb + (s ? OFF_AS1 : OFF_AS0) + aoff;
        const uint32_t bbase = sb + (s ? OFF_BS1 : OFF_BS0) + boff;
        #pragma unroll
        for (int ks = 0; ks < KC / 16; ++ks) {
            uint32_t a[4][4], b[8][2];
            #pragma unroll
            for (int mt = 0; mt < 4; ++mt)
                ldsm4(a[mt][0], a[mt][1], a[mt][2], a[mt][3],
                      abase + (uint32_t)(mt * 16 * STRIDE_B + ks * 32));
            #pragma unroll
            for (int nt2 = 0; nt2 < 4; ++nt2) {
                uint32_t r0, r1, r2, r3;
                ldsm4(r0, r1, r2, r3,
                      bbase + (uint32_t)(nt2 * 16 * STRIDE_B + ks * 32));
                b[nt2 * 2][0] = r0;      b[nt2 * 2][1] = r2;
                b[nt2 * 2 + 1][0] = r1;  b[nt2 * 2 + 1][1] = r3;
            }
            #pragma unroll
            for (int mt = 0; mt < 4; ++mt)
                #pragma unroll
                for (int nt = 0; nt < 8; ++nt)
                    mma16816(c[mt][nt], a[mt], b[nt]);
        }

        if (cc < KCHUNKS - 1) {
            cp_wait0();           // drain B for next chunk; overlaps with store_A below
            store_A(s ^ 1);       // regs -> next-stage A tile (pure FMA/STS, no dependence on cp)
        }
        __syncthreads();
    }

    // gating epilogue: fold this CTA's 128 channels into per-row partial logits
    {
        const int g = lane >> 2, tig = lane & 3;
        float racc[8];
        #pragma unroll
        for (int i = 0; i < 8; ++i) racc[i] = 0.0f;
        #pragma unroll
        for (int mt = 0; mt < 4; ++mt) {
            #pragma unroll
            for (int nt = 0; nt < 8; ++nt) {
                const int ch = ((n0 + nt * 8) >> 1) + tig;     // local channel 0..127
                const float vb = sVb[ch], ub = sUb[ch], wwc = sww[ch];
                float tv0 = tanha(c[mt][nt][0] + vb);
                float su0 = 0.5f * tanha(0.5f * (c[mt][nt][1] + ub)) + 0.5f;
                float tv1 = tanha(c[mt][nt][2] + vb);
                float su1 = 0.5f * tanha(0.5f * (c[mt][nt][3] + ub)) + 0.5f;
                racc[mt * 2]     += tv0 * su0 * wwc;
                racc[mt * 2 + 1] += tv1 * su1 * wwc;
            }
        }
        #pragma unroll
        for (int i = 0; i < 8; ++i) {
            float v = racc[i];
            v += __shfl_xor_sync(0xffffffffu, v, 1);
            v += __shfl_xor_sync(0xffffffffu, v, 2);
            if (tig == 0) {
                const int r = m0 + (i >> 1) * 16 + g + (i & 1) * 8;
                atomicAdd(&slog[r], v);
            }
        }
    }
    __syncthreads();
    if (tid < 128) g_att2[nc][baseRow + tid] = slog[tid];
}

// ---------------- masked softmax ----------------
__global__ void __launch_bounds__(1024) mil_softmax_kernel(const int* __restrict__ npw,
                                                           float* __restrict__ out) {
    __shared__ float red[1024];
    const int b = blockIdx.x;
    const int t = threadIdx.x;
    // nonpad may be int64 (values in [1,8192] => odd words zero) or int32.
    const bool is64 = (npw[1] == 0) && (npw[3] == 0) && (npw[5] == 0) && (npw[7] == 0);
    const int np = is64 ? npw[2 * b] : npw[b];
    const float* a0 = g_att2[0] + b * PZ;
    const float* a1 = g_att2[1] + b * PZ;
    float* o = out + b * PZ;

    float e[8];
    float mx = -3.4e38f;
    #pragma unroll
    for (int j = 0; j < 8; ++j) {
        int p = t + j * 1024;
        float v = (p < np) ? (a0[p] + a1[p]) : -3.4e38f;
        e[j] = v;
        mx = fmaxf(mx, v);
    }
    red[t] = mx;
    __syncthreads();
    for (int s = 512; s > 0; s >>= 1) {
        if (t < s) red[t] = fmaxf(red[t], red[t + s]);
        __syncthreads();
    }
    mx = red[0];
    __syncthreads();

    float sum = 0.0f;
    #pragma unroll
    for (int j = 0; j < 8; ++j) {
        int p = t + j * 1024;
        float v = (p < np) ? expf(e[j] - mx) : 0.0f;
        e[j] = v;
        sum += v;
    }
    red[t] = sum;
    __syncthreads();
    for (int s = 512; s > 0; s >>= 1) {
        if (t < s) red[t] += red[t + s];
        __syncthreads();
    }
    const float inv = 1.0f / red[0];
    #pragma unroll
    for (int j = 0; j < 8; ++j) {
        o[t + j * 1024] = e[j] * inv;
    }
}

// ---------------- launch ----------------
extern "C" void kernel_launch(void* const* d_in, const int* in_sizes, int n_in,
                              void* d_out, int out_size) {
    (void)in_sizes; (void)n_in; (void)out_size;
    const float* x   = (const float*)d_in[0];
    const int*   npw = (const int*)d_in[1];
    const float* V_w = (const float*)d_in[2];
    const float* V_b = (const float*)d_in[3];
    const float* U_w = (const float*)d_in[4];
    const float* U_b = (const float*)d_in[5];
    const float* w_w = (const float*)d_in[6];
    float* out = (float*)d_out;

    cudaFuncSetAttribute(mil_gemm_kernel,
                         cudaFuncAttributeMaxDynamicSharedMemorySize, SMEM_TOTAL);

    prep_w_kernel<<<(2 * FI * FZ) / 256, 256>>>(V_w, U_w);
    mil_gemm_kernel<<<GRID, THREADS, SMEM_TOTAL>>>(x, V_b, U_b, w_w);
    mil_softmax_kernel<<<BZ, 1024>>>(npw, out);
}